// round 5
// baseline (speedup 1.0000x reference)
#include <cuda_runtime.h>
#include <cstdint>

// Problem constants (fixed by the reference)
#define B_ 32
#define S_ 512
#define P_ 8
#define K_ 256
#define D_ 64
#define NROWS (B_ * S_ * P_)   // 131072 rows of K=256 logits each

#define FULL 0xffffffffu
#define NEG_INF __int_as_float(0xff800000)

// Rotation multipliers 2^r for threefry rounds, loaded at RUNTIME so ptxas
// cannot strength-reduce the widening multiply back into SHF (alu pipe).
// (u64)x * 2^r gives lo = x<<r, hi = x>>(32-r); lo|hi == rotl(x, r).
// This moves the rotate onto the fma pipe (IMAD.WIDE.U32), leaving only one
// alu op (a single 3-input LOP3) per threefry round.
__device__ uint32_t d_rotmul[8] = {
    1u << 13, 1u << 15, 1u << 26, 1u << 6,
    1u << 17, 1u << 29, 1u << 16, 1u << 24
};

struct RotM { uint32_t m[8]; };

__device__ __forceinline__ void tf_round(uint32_t& x0, uint32_t& x1, uint32_t mul) {
    x0 += x1;
    unsigned long long w = (unsigned long long)x1 * mul;   // IMAD.WIDE.U32 (fma)
    x1 = ((uint32_t)w | (uint32_t)(w >> 32)) ^ x0;          // one LOP3 (alu)
}

// ---------------------------------------------------------------------------
// JAX threefry2x32, partitionable mode, key = jax.random.key(42) -> (0, 42).
// Per-element 64-bit counter = flat index i (hi word 0). Draw = out0 ^ out1.
// ---------------------------------------------------------------------------
__device__ __forceinline__ uint32_t threefry_bits(uint32_t i, const RotM& R) {
    const uint32_t ks0 = 0u;
    const uint32_t ks1 = 42u;
    const uint32_t ks2 = 0x1BD11BDAu ^ 0u ^ 42u;
    uint32_t x0 = 0u + ks0;
    uint32_t x1 = i + ks1;

    tf_round(x0, x1, R.m[0]); tf_round(x0, x1, R.m[1]);
    tf_round(x0, x1, R.m[2]); tf_round(x0, x1, R.m[3]);
    x0 += ks1; x1 += ks2 + 1u;
    tf_round(x0, x1, R.m[4]); tf_round(x0, x1, R.m[5]);
    tf_round(x0, x1, R.m[6]); tf_round(x0, x1, R.m[7]);
    x0 += ks2; x1 += ks0 + 2u;
    tf_round(x0, x1, R.m[0]); tf_round(x0, x1, R.m[1]);
    tf_round(x0, x1, R.m[2]); tf_round(x0, x1, R.m[3]);
    x0 += ks0; x1 += ks1 + 3u;
    tf_round(x0, x1, R.m[4]); tf_round(x0, x1, R.m[5]);
    tf_round(x0, x1, R.m[6]); tf_round(x0, x1, R.m[7]);
    x0 += ks1; x1 += ks2 + 4u;
    tf_round(x0, x1, R.m[0]); tf_round(x0, x1, R.m[1]);
    tf_round(x0, x1, R.m[2]); tf_round(x0, x1, R.m[3]);
    x0 += ks2; x1 += ks0 + 5u;

    return x0 ^ x1;
}

// Exact path, bit-identical to the reference fp32 computation. INLINE (no CALL).
__device__ __forceinline__ float exact_score(const float* __restrict__ erow,
                                             uint32_t row_base, int k,
                                             const RotM& R) {
    uint32_t bits = threefry_bits(row_base + (uint32_t)k, R);
    float f = __uint_as_float((bits >> 9) | 0x3f800000u) - 1.0f;  // u in [0,1)
    float u = fmaxf(f, 1.17549435e-38f);
    float g = -logf(-logf(u));
    return __ldg(erow + k) + g;   // e reloaded from L1 (hot)
}

// ---------------------------------------------------------------------------
// One warp per (b, s, p) row. Screen-then-verify:
//   s_j = e_j - C2*float(bits(v_j)),  v_j = 1 - u_j  (exact in fp32)
//   exact_j <= s_j + 127*ln2 + eps   (g <= -ln v, exponent-bit-hack lower-
//                                     bounds log2 v; eps covers fp rounding)
// Exact scores are computed only for the top-s element (-> LB) and the few
// elements whose bound clears LB. All true argmax candidates provably survive.
// ---------------------------------------------------------------------------
__global__ void __launch_bounds__(256) symbolic_gumbel_kernel(
    const int*   __restrict__ inputs,       // [B, S] int32
    const float* __restrict__ pattern_map,  // [N_CAT, P, K]
    const float* __restrict__ symbols,      // [K, D]
    float*       __restrict__ out)          // [B, S, P*D]
{
    const int warp = (blockIdx.x * blockDim.x + threadIdx.x) >> 5;
    const int lane = threadIdx.x & 31;

    // Load rotation multipliers once (two LDG.128, L1-resident, uniform).
    RotM R;
    {
        uint4 a = *reinterpret_cast<const uint4*>(&d_rotmul[0]);
        uint4 b = *reinterpret_cast<const uint4*>(&d_rotmul[4]);
        R.m[0] = a.x; R.m[1] = a.y; R.m[2] = a.z; R.m[3] = a.w;
        R.m[4] = b.x; R.m[5] = b.y; R.m[6] = b.z; R.m[7] = b.w;
    }

    const int row = warp;                    // grid covers exactly NROWS warps
    const int bs  = row >> 3;
    const int p   = row & 7;
    const int cat = __ldg(&inputs[bs]);

    const float* erow = pattern_map + ((size_t)cat * P_ + p) * K_;
    const uint32_t row_base = (uint32_t)row * (uint32_t)K_;
    const uint32_t base = row_base + (uint32_t)(lane * 8);

    const float4* e4 = reinterpret_cast<const float4*>(erow + lane * 8);
    float4 ea = __ldg(&e4[0]);
    float4 eb = __ldg(&e4[1]);
    float e[8] = {ea.x, ea.y, ea.z, ea.w, eb.x, eb.y, eb.z, eb.w};

    // ---- Pass 1: cheap bounds (shifted by -127*ln2), lane max only ----
    const float C2 = 8.2629582e-8f;   // ln2 * 2^-23
    float s[8];
    float smax = NEG_INF;
#pragma unroll
    for (int j = 0; j < 8; j++) {
        uint32_t bits = threefry_bits(base + (uint32_t)j, R);
        float w  = __uint_as_float((bits >> 9) | 0x3f800000u);  // 1+u in [1,2)
        float v  = 2.0f - w;                                    // 1-u, exact
        float vf = (float)__float_as_int(v);
        float sj = fmaf(vf, -C2, e[j]);
        s[j] = sj;
        smax = fmaxf(smax, sj);                                 // FMNMX, no index
    }

    // Warp max of the bound (value only)
#pragma unroll
    for (int off = 16; off > 0; off >>= 1)
        smax = fmaxf(smax, __shfl_xor_sync(FULL, smax, off));

    // Post-hoc owner: lowest j in this lane matching smax (if any)
    int jm = 8;
#pragma unroll
    for (int j = 7; j >= 0; j--)
        if (s[j] == smax) jm = j;
    unsigned ball = __ballot_sync(FULL, jm < 8);
    int owner = __ffs(ball) - 1;

    // ---- LB: exact score of the top-bound element (inline, one lane) ----
    int   k_top_l = lane * 8 + jm;
    float exl = 0.0f;
    if (lane == owner) exl = exact_score(erow, row_base, k_top_l, R);
    const float LB    = __shfl_sync(FULL, exl, owner);
    const int   k_top = __shfl_sync(FULL, k_top_l, owner);

    // candidates: s_j >= LB - 127*ln2 - slack
    const float thresh = LB - 88.029691931f - 1e-3f;

    // ---- Pass 2: exact scores for survivors only (~2 per row) ----
    float bestx = LB;
    int   bestk = k_top;
#pragma unroll
    for (int j = 0; j < 8; j++) {
        bool cand = (s[j] >= thresh);
        if (__any_sync(FULL, cand)) {
            int   k = lane * 8 + j;
            float x = NEG_INF;
            if (cand) x = exact_score(erow, row_base, k, R);
            if (x > bestx || (x == bestx && k < bestk)) { bestx = x; bestk = k; }
        }
    }

    // Warp argmax with first-index tie-break (matches jnp.argmax)
#pragma unroll
    for (int off = 16; off > 0; off >>= 1) {
        float ob = __shfl_xor_sync(FULL, bestx, off);
        int   ok = __shfl_xor_sync(FULL, bestk, off);
        if (ob > bestx || (ob == bestx && ok < bestk)) { bestx = ob; bestk = ok; }
    }

    // Copy symbols[bestk, :] (64 floats = 256B) to out[row, :], 2 floats/lane
    const float2* srow = reinterpret_cast<const float2*>(symbols + (size_t)bestk * D_);
    float2 val = __ldg(&srow[lane]);
    float2* orow = reinterpret_cast<float2*>(out + (size_t)row * D_);
    orow[lane] = val;
}

extern "C" void kernel_launch(void* const* d_in, const int* in_sizes, int n_in,
                              void* d_out, int out_size) {
    const int*   inputs      = (const int*)  d_in[0];  // [32, 512] int32
    const float* pattern_map = (const float*)d_in[1];  // [50000, 8, 256]
    const float* symbols     = (const float*)d_in[2];  // [256, 64]
    // d_in[3] = tau (== 1.0, positive): argmax invariant; straight-through
    // weights are one-hot to fp32 rounding, so tau is unused.
    float* out = (float*)d_out;                        // [32, 512, 512]

    const int threads = 256;                 // 8 warps -> 8 rows per block
    const int blocks  = NROWS / 8;           // 16384
    symbolic_gumbel_kernel<<<blocks, threads>>>(inputs, pattern_map, symbols, out);
}

// round 6
// speedup vs baseline: 1.4685x; 1.4685x over previous
#include <cuda_runtime.h>
#include <cstdint>

// Problem constants (fixed by the reference)
#define B_ 32
#define S_ 512
#define P_ 8
#define K_ 256
#define D_ 64
#define NROWS (B_ * S_ * P_)   // 131072 rows of K=256 logits each

#define FULL 0xffffffffu
#define NEG_INF __int_as_float(0xff800000)
#define LN2F 0.69314718055994530942f

// Runtime '1' so ptxas cannot strength-reduce mad.lo back to IADD3: forces the
// threefry adds onto the fma pipe (IMAD), leaving the alu pipe to SHF/LOP3 only.
__device__ uint32_t d_one = 1u;

__device__ __forceinline__ uint32_t rotl32(uint32_t x, int r) {
    return __funnelshift_l(x, x, r);
}
// a + b as IMAD: b*one + a  (fma pipe)
__device__ __forceinline__ uint32_t madd(uint32_t a, uint32_t b, uint32_t one) {
    uint32_t r;
    asm("mad.lo.u32 %0, %1, %2, %3;" : "=r"(r) : "r"(b), "r"(one), "r"(a));
    return r;
}
__device__ __forceinline__ float lg2a(float x) {
    float r;
    asm("lg2.approx.f32 %0, %1;" : "=f"(r) : "f"(x));
    return r;
}

// ---------------------------------------------------------------------------
// JAX threefry2x32, partitionable mode, key (0, 42); counter = (0, i).
// Draw = x0 ^ x1. ks = (0, 42, 0x1BD11BDA^42). Adds forced to fma pipe.
// ---------------------------------------------------------------------------
__device__ __forceinline__ uint32_t threefry_bits(uint32_t i, uint32_t one) {
    const uint32_t KS1 = 42u;
    const uint32_t KS2 = 0x1BD11BDAu ^ 42u;
    uint32_t x1 = madd(i, KS1, one);   // i + 42
    uint32_t x0 = x1;                  // round 1: x0 = 0 + x1
    x1 = rotl32(x1, 13) ^ x0;
#define RND(r) { x0 = madd(x0, x1, one); x1 = rotl32(x1, (r)) ^ x0; }
    RND(15) RND(26) RND(6)
    x0 = madd(x0, KS1, one);      x1 = madd(x1, KS2 + 1u, one);
    RND(17) RND(29) RND(16) RND(24)
    x0 = madd(x0, KS2, one);      x1 = madd(x1, 2u, one);        // ks0 = 0
    RND(13) RND(15) RND(26) RND(6)
    /* x0 += ks0 == 0 */          x1 = madd(x1, KS1 + 3u, one);
    RND(17) RND(29) RND(16) RND(24)
    x0 = madd(x0, KS1, one);      x1 = madd(x1, KS2 + 4u, one);
    RND(13) RND(15) RND(26) RND(6)
    x0 = madd(x0, KS2, one);      x1 = madd(x1, 5u, one);
#undef RND
    return x0 ^ x1;
}

// Exact path: bit-identical to the reference fp32 computation (accurate logf).
__device__ __forceinline__ float exact_score(const float* __restrict__ erow,
                                             uint32_t row_base, int k, uint32_t one) {
    uint32_t bits = threefry_bits(row_base + (uint32_t)k, one);
    float f = __uint_as_float((bits >> 9) | 0x3f800000u) - 1.0f;  // u in [0,1)
    float u = fmaxf(f, 1.17549435e-38f);
    float g = -logf(-logf(u));
    return __ldg(erow + k) + g;
}

// ---------------------------------------------------------------------------
// One warp per (b, s, p) row. Fast scores via lg2.approx (MUFU pipe):
//   s_j = e_j - ln2 * lg2(-lg2(u_j)*ln2),  |s_j - exact_j| <= ~2.5e-5.
// If exactly ONE element has s_j >= smax - 4e-4, it is provably the reference
// argmax (no exact eval at all). Else (~50 rows in 131072) rerun the bit-exact
// accurate-logf path on the candidate band with first-index tie-break.
// ---------------------------------------------------------------------------
__global__ void __launch_bounds__(256) symbolic_gumbel_kernel(
    const int*   __restrict__ inputs,       // [B, S] int32
    const float* __restrict__ pattern_map,  // [N_CAT, P, K]
    const float* __restrict__ symbols,      // [K, D]
    float*       __restrict__ out)          // [B, S, P*D]
{
    const int warp = (blockIdx.x * blockDim.x + threadIdx.x) >> 5;
    const int lane = threadIdx.x & 31;
    const uint32_t one = d_one;              // runtime 1 (uniform)

    const int row = warp;                    // grid covers exactly NROWS warps
    const int bs  = row >> 3;
    const int p   = row & 7;
    const int cat = __ldg(&inputs[bs]);

    const float* erow = pattern_map + ((size_t)cat * P_ + p) * K_;
    const uint32_t row_base = (uint32_t)row * (uint32_t)K_;
    const uint32_t base = row_base + (uint32_t)(lane * 8);

    const float4* e4 = reinterpret_cast<const float4*>(erow + lane * 8);
    float4 ea = __ldg(&e4[0]);
    float4 eb = __ldg(&e4[1]);
    float e[8] = {ea.x, ea.y, ea.z, ea.w, eb.x, eb.y, eb.z, eb.w};

    // ---- Pass 1: fast scores, max only ----
    float s[8];
    float smax = NEG_INF;
#pragma unroll
    for (int j = 0; j < 8; j++) {
        uint32_t bits = threefry_bits(base + (uint32_t)j, one);
        float f  = __uint_as_float((bits >> 9) | 0x3f800000u) - 1.0f;  // u in [0,1)
        float u  = fmaxf(f, 1.17549435e-38f);
        float yl = lg2a(u) * (-LN2F);          // = -ln(u) > 0
        float x  = fmaf(lg2a(yl), -LN2F, e[j]);  // e_j - ln(-ln u)
        s[j] = x;
        smax = fmaxf(smax, x);
    }
#pragma unroll
    for (int off = 16; off > 0; off >>= 1)
        smax = fmaxf(smax, __shfl_xor_sync(FULL, smax, off));

    // ---- Candidate band ----
    const float thr = smax - 4e-4f;
    int cnt = 0, jm = 8;
#pragma unroll
    for (int j = 0; j < 8; j++) {
        bool c = (s[j] >= thr);
        cnt += c;
        if (c && jm == 8) jm = j;
    }
    int tot = cnt;
#pragma unroll
    for (int off = 16; off > 0; off >>= 1)
        tot += __shfl_xor_sync(FULL, tot, off);

    int bestk;
    if (tot == 1) {
        // Unique candidate == reference argmax (error band is provable).
        unsigned ball = __ballot_sync(FULL, cnt > 0);
        int owner = __ffs(ball) - 1;
        bestk = __shfl_sync(FULL, lane * 8 + jm, owner);
    } else {
        // Rare: exact (reference-identical) scores on the candidate band.
        float bestx = NEG_INF;
        bestk = K_;
#pragma unroll
        for (int j = 0; j < 8; j++) {
            bool cand = (s[j] >= thr);
            if (__any_sync(FULL, cand)) {
                int   k = lane * 8 + j;
                float x = NEG_INF;
                if (cand) x = exact_score(erow, row_base, k, one);
                if (x > bestx || (x == bestx && k < bestk)) { bestx = x; bestk = k; }
            }
        }
#pragma unroll
        for (int off = 16; off > 0; off >>= 1) {
            float ob = __shfl_xor_sync(FULL, bestx, off);
            int   ok = __shfl_xor_sync(FULL, bestk, off);
            if (ob > bestx || (ob == bestx && ok < bestk)) { bestx = ob; bestk = ok; }
        }
    }

    // Copy symbols[bestk, :] (64 floats = 256B) to out[row, :], 2 floats/lane
    const float2* srow = reinterpret_cast<const float2*>(symbols + (size_t)bestk * D_);
    float2 val = __ldg(&srow[lane]);
    float2* orow = reinterpret_cast<float2*>(out + (size_t)row * D_);
    orow[lane] = val;
}

extern "C" void kernel_launch(void* const* d_in, const int* in_sizes, int n_in,
                              void* d_out, int out_size) {
    const int*   inputs      = (const int*)  d_in[0];  // [32, 512] int32
    const float* pattern_map = (const float*)d_in[1];  // [50000, 8, 256]
    const float* symbols     = (const float*)d_in[2];  // [256, 64]
    // d_in[3] = tau (== 1.0, positive): argmax invariant; straight-through
    // weights are one-hot to fp32 rounding, so tau is unused.
    float* out = (float*)d_out;                        // [32, 512, 512]

    const int threads = 256;                 // 8 warps -> 8 rows per block
    const int blocks  = NROWS / 8;           // 16384
    symbolic_gumbel_kernel<<<blocks, threads>>>(inputs, pattern_map, symbols, out);
}

// round 7
// speedup vs baseline: 1.5821x; 1.0774x over previous
#include <cuda_runtime.h>
#include <cstdint>

// Problem constants (fixed by the reference)
#define B_ 32
#define S_ 512
#define P_ 8
#define K_ 256
#define D_ 64
#define NROWS (B_ * S_ * P_)   // 131072 rows of K=256 logits each

#define FULL 0xffffffffu
#define NEG_INF __int_as_float(0xff800000)
#define LN2F 0.69314718055994530942f

__device__ __forceinline__ uint32_t rotl32(uint32_t x, int r) {
    return __funnelshift_l(x, x, r);
}
__device__ __forceinline__ float lg2a(float x) {
    float r;
    asm("lg2.approx.f32 %0, %1;" : "=f"(r) : "f"(x));
    return r;
}

// ---------------------------------------------------------------------------
// JAX threefry2x32, partitionable mode, key (0, 42); counter = (0, i).
// Draw = x0 ^ x1. ks = (0, 42, 0x1BD11BDA^42). Plain adds: ptxas alternates
// IMAD/IADD3 across fma/alu pipes on its own.
// ---------------------------------------------------------------------------
__device__ __forceinline__ uint32_t threefry_bits(uint32_t i) {
    const uint32_t KS1 = 42u;
    const uint32_t KS2 = 0x1BD11BDAu ^ 42u;
    uint32_t x1 = i + KS1;
    uint32_t x0 = x1;                  // round 1: x0 = 0 + x1
    x1 = rotl32(x1, 13) ^ x0;
#define RND(r) { x0 += x1; x1 = rotl32(x1, (r)) ^ x0; }
    RND(15) RND(26) RND(6)
    x0 += KS1;  x1 += KS2 + 1u;
    RND(17) RND(29) RND(16) RND(24)
    x0 += KS2;  x1 += 2u;              // ks0 = 0
    RND(13) RND(15) RND(26) RND(6)
    /* x0 += ks0 == 0 */ x1 += KS1 + 3u;
    RND(17) RND(29) RND(16) RND(24)
    x0 += KS1;  x1 += KS2 + 4u;
    RND(13) RND(15) RND(26) RND(6)
    x0 += KS2;  x1 += 5u;
#undef RND
    return x0 ^ x1;
}

// Exact path: bit-identical to the reference fp32 computation (accurate logf).
__device__ __forceinline__ float exact_score(const float* __restrict__ erow,
                                             uint32_t row_base, int k) {
    uint32_t bits = threefry_bits(row_base + (uint32_t)k);
    float f = __uint_as_float((bits >> 9) | 0x3f800000u) - 1.0f;  // u in [0,1)
    float u = fmaxf(f, 1.17549435e-38f);
    float g = -logf(-logf(u));
    return __ldg(erow + k) + g;
}

// ---------------------------------------------------------------------------
// One warp per (b, s, p) row. Fast scores via lg2.approx (MUFU pipe):
//   s_j = e_j - ln2 * lg2(-lg2(u_j)*ln2),  |s_j - exact_j| <= ~2.5e-5.
// If exactly ONE element has s_j >= smax - 4e-4, it is provably the reference
// argmax (no exact eval at all). Else (~50 rows in 131072) rerun the bit-exact
// accurate-logf path on the candidate band with first-index tie-break.
// ---------------------------------------------------------------------------
__global__ void __launch_bounds__(256, 8) symbolic_gumbel_kernel(
    const int*   __restrict__ inputs,       // [B, S] int32
    const float* __restrict__ pattern_map,  // [N_CAT, P, K]
    const float* __restrict__ symbols,      // [K, D]
    float*       __restrict__ out)          // [B, S, P*D]
{
    const int warp = (blockIdx.x * blockDim.x + threadIdx.x) >> 5;
    const int lane = threadIdx.x & 31;

    const int row = warp;                    // grid covers exactly NROWS warps
    const int bs  = row >> 3;
    const int p   = row & 7;
    const int cat = __ldg(&inputs[bs]);

    const float* erow = pattern_map + ((size_t)cat * P_ + p) * K_;
    const uint32_t row_base = (uint32_t)row * (uint32_t)K_;
    const uint32_t base = row_base + (uint32_t)(lane * 8);

    const float4* e4 = reinterpret_cast<const float4*>(erow + lane * 8);
    float4 ea = __ldg(&e4[0]);
    float4 eb = __ldg(&e4[1]);
    float e[8] = {ea.x, ea.y, ea.z, ea.w, eb.x, eb.y, eb.z, eb.w};

    // ---- Pass 1: fast scores, max only ----
    float s[8];
    float smax = NEG_INF;
#pragma unroll
    for (int j = 0; j < 8; j++) {
        uint32_t bits = threefry_bits(base + (uint32_t)j);
        float f  = __uint_as_float((bits >> 9) | 0x3f800000u) - 1.0f;  // u in [0,1)
        float u  = fmaxf(f, 1.17549435e-38f);
        float yl = lg2a(u) * (-LN2F);            // = -ln(u) > 0
        float x  = fmaf(lg2a(yl), -LN2F, e[j]);  // e_j - ln(-ln u)
        s[j] = x;
        smax = fmaxf(smax, x);
    }
#pragma unroll
    for (int off = 16; off > 0; off >>= 1)
        smax = fmaxf(smax, __shfl_xor_sync(FULL, smax, off));

    // ---- Candidate band ----
    const float thr = smax - 4e-4f;
    int cnt = 0, jm = 8;
#pragma unroll
    for (int j = 0; j < 8; j++) {
        bool c = (s[j] >= thr);
        cnt += c;
        if (c && jm == 8) jm = j;
    }
    int tot = cnt;
#pragma unroll
    for (int off = 16; off > 0; off >>= 1)
        tot += __shfl_xor_sync(FULL, tot, off);

    int bestk;
    if (tot == 1) {
        // Unique candidate == reference argmax (error band is provable).
        unsigned ball = __ballot_sync(FULL, cnt > 0);
        int owner = __ffs(ball) - 1;
        bestk = __shfl_sync(FULL, lane * 8 + jm, owner);
    } else {
        // Rare: exact (reference-identical) scores on the candidate band.
        float bestx = NEG_INF;
        bestk = K_;
#pragma unroll
        for (int j = 0; j < 8; j++) {
            bool cand = (s[j] >= thr);
            if (__any_sync(FULL, cand)) {
                int   k = lane * 8 + j;
                float x = NEG_INF;
                if (cand) x = exact_score(erow, row_base, k);
                if (x > bestx || (x == bestx && k < bestk)) { bestx = x; bestk = k; }
            }
        }
#pragma unroll
        for (int off = 16; off > 0; off >>= 1) {
            float ob = __shfl_xor_sync(FULL, bestx, off);
            int   ok = __shfl_xor_sync(FULL, bestk, off);
            if (ob > bestx || (ob == bestx && ok < bestk)) { bestx = ob; bestk = ok; }
        }
    }

    // Copy symbols[bestk, :] (64 floats = 256B) to out[row, :], 2 floats/lane
    const float2* srow = reinterpret_cast<const float2*>(symbols + (size_t)bestk * D_);
    float2 val = __ldg(&srow[lane]);
    float2* orow = reinterpret_cast<float2*>(out + (size_t)row * D_);
    orow[lane] = val;
}

extern "C" void kernel_launch(void* const* d_in, const int* in_sizes, int n_in,
                              void* d_out, int out_size) {
    const int*   inputs      = (const int*)  d_in[0];  // [32, 512] int32
    const float* pattern_map = (const float*)d_in[1];  // [50000, 8, 256]
    const float* symbols     = (const float*)d_in[2];  // [256, 64]
    // d_in[3] = tau (== 1.0, positive): argmax invariant; straight-through
    // weights are one-hot to fp32 rounding, so tau is unused.
    float* out = (float*)d_out;                        // [32, 512, 512]

    const int threads = 256;                 // 8 warps -> 8 rows per block
    const int blocks  = NROWS / 8;           // 16384
    symbolic_gumbel_kernel<<<blocks, threads>>>(inputs, pattern_map, symbols, out);
}